// round 13
// baseline (speedup 1.0000x reference)
#include <cuda_runtime.h>
#include <cuda_bf16.h>
#include <math.h>
#include <cstdint>

// Problem constants
#define BB   8
#define CCH  512
#define C8   64
#define NN   2048
#define OUT_OFF (BB*CCH*NN)   // start of attention region in d_out (floats)

typedef unsigned long long u64;

// Scratch: q/k as 2-way bf16 split [b][n][comp*64 + o], comp 0=hi, 1=mid
__device__ __nv_bfloat16 g_qs[BB*NN*128];
__device__ __nv_bfloat16 g_ks[BB*NN*128];
__device__ float g_v[BB*CCH*NN];           // slow path only (gamma != 0)

// ---- packed f32x2 helpers ------------------------------------------------
__device__ __forceinline__ u64 pack2(float x) {
    u64 r; asm("mov.b64 %0, {%1, %1};" : "=l"(r) : "f"(x)); return r;
}
__device__ __forceinline__ void ffma2(u64& d, u64 a, u64 b) {
    asm("fma.rn.f32x2 %0, %1, %2, %3;" : "=l"(d) : "l"(a), "l"(b), "l"(d));
}
__device__ __forceinline__ float2 unpack2(u64 v) {
    float2 f; asm("mov.b64 {%0, %1}, %2;" : "=f"(f.x), "=f"(f.y) : "l"(v)); return f;
}

// ---- sm_80-class tensor helpers (legal on plain sm_103 target) -----------
__device__ __forceinline__ uint32_t smem_u32(const void* p) {
    uint32_t a;
    asm("{ .reg .u64 t; cvta.to.shared.u64 t, %1; cvt.u32.u64 %0, t; }" : "=r"(a) : "l"(p));
    return a;
}
#define LDSM_X4(r0, r1, r2, r3, addr) \
    asm volatile("ldmatrix.sync.aligned.m8n8.x4.shared.b16 {%0,%1,%2,%3}, [%4];" \
        : "=r"(r0), "=r"(r1), "=r"(r2), "=r"(r3) : "r"(addr))
#define CP_ASYNC16(dst, src) \
    asm volatile("cp.async.cg.shared.global [%0], [%1], 16;" :: "r"(dst), "l"(src) : "memory")
#define CP_COMMIT() asm volatile("cp.async.commit_group;" ::: "memory")

__device__ __forceinline__ void mma_bf16(float& c0, float& c1, float& c2, float& c3,
                                         uint32_t a0, uint32_t a1, uint32_t a2, uint32_t a3,
                                         uint32_t b0, uint32_t b1) {
    asm volatile(
        "mma.sync.aligned.m16n8k16.row.col.f32.bf16.bf16.f32 "
        "{%0,%1,%2,%3}, {%4,%5,%6,%7}, {%8,%9}, {%0,%1,%2,%3};"
        : "+f"(c0), "+f"(c1), "+f"(c2), "+f"(c3)
        : "r"(a0), "r"(a1), "r"(a2), "r"(a3), "r"(b0), "r"(b1));
}

// ---------------------------------------------------------------------------
// Fused q+k projection (FFMA2) -> 2-way bf16 split, layout [b][n][comp*64+o].
// which==1 (k from x) additionally copies x into out region (out = x).
// ---------------------------------------------------------------------------
__global__ __launch_bounds__(128, 3) void qk_kernel(
    const float* __restrict__ x, const float* __restrict__ y,
    const float* __restrict__ Wq, const float* __restrict__ bq,
    const float* __restrict__ Wk, const float* __restrict__ bk,
    float* __restrict__ outx)
{
    const int which = blockIdx.z;
    const float* in   = which ? x  : y;
    const float* W    = which ? Wk : Wq;
    const float* bias = which ? bk : bq;

    const int t  = threadIdx.x;
    const int tx = t & 15;
    const int ty = t >> 4;
    const int n0 = tx * 8;
    const int o0 = ty * 8;
    const int nb = blockIdx.x * 128;
    const int b  = blockIdx.y;

    __shared__ float wt[32][68];
    __shared__ float it[32][128];

    u64 acc[8][4];
    #pragma unroll
    for (int j = 0; j < 8; j++)
        #pragma unroll
        for (int i = 0; i < 4; i++) acc[j][i] = 0ull;

    for (int c0 = 0; c0 < CCH; c0 += 32) {
        __syncthreads();
        #pragma unroll
        for (int i = 0; i < 4; i++) {
            int l  = t + i * 128;
            int o  = l >> 3;
            int c4 = (l & 7) * 4;
            float4 w4 = *(const float4*)&W[o * CCH + c0 + c4];
            wt[c4 + 0][o] = w4.x; wt[c4 + 1][o] = w4.y;
            wt[c4 + 2][o] = w4.z; wt[c4 + 3][o] = w4.w;
        }
        #pragma unroll
        for (int i = 0; i < 8; i++) {
            int l  = t + i * 128;
            int cc = l >> 5;
            int n4 = (l & 31) * 4;
            size_t gidx = ((size_t)(b * CCH + c0 + cc) * NN) + nb + n4;
            float4 v = *(const float4*)&in[gidx];
            *(float4*)&it[cc][n4] = v;
            if (which) *(float4*)&outx[gidx] = v;   // out = x (residual copy)
        }
        __syncthreads();

        #pragma unroll 4
        for (int cc = 0; cc < 32; cc++) {
            float4 w0 = *(const float4*)&wt[cc][o0];
            float4 w1 = *(const float4*)&wt[cc][o0 + 4];
            u64 wp[8] = {pack2(w0.x), pack2(w0.y), pack2(w0.z), pack2(w0.w),
                         pack2(w1.x), pack2(w1.y), pack2(w1.z), pack2(w1.w)};
            ulonglong2 ia = *(const ulonglong2*)&it[cc][n0];
            ulonglong2 ib = *(const ulonglong2*)&it[cc][n0 + 4];
            u64 iv[4] = {ia.x, ia.y, ib.x, ib.y};
            #pragma unroll
            for (int j = 0; j < 8; j++)
                #pragma unroll
                for (int i = 0; i < 4; i++)
                    ffma2(acc[j][i], wp[j], iv[i]);
        }
    }

    float val[8][8];
    #pragma unroll
    for (int j = 0; j < 8; j++) {
        float bb = bias[o0 + j];
        float2 p0 = unpack2(acc[j][0]);
        float2 p1 = unpack2(acc[j][1]);
        float2 p2 = unpack2(acc[j][2]);
        float2 p3 = unpack2(acc[j][3]);
        val[j][0] = p0.x + bb; val[j][1] = p0.y + bb;
        val[j][2] = p1.x + bb; val[j][3] = p1.y + bb;
        val[j][4] = p2.x + bb; val[j][5] = p2.y + bb;
        val[j][6] = p3.x + bb; val[j][7] = p3.y + bb;
    }

    #pragma unroll
    for (int i = 0; i < 8; i++) {
        uint32_t hi[4], mi[4];
        #pragma unroll
        for (int jp = 0; jp < 4; jp++) {
            float v0 = val[2*jp][i], v1 = val[2*jp+1][i];
            __nv_bfloat16 h0 = __float2bfloat16(v0);
            __nv_bfloat16 m0 = __float2bfloat16(v0 - __bfloat162float(h0));
            __nv_bfloat16 h1 = __float2bfloat16(v1);
            __nv_bfloat16 m1 = __float2bfloat16(v1 - __bfloat162float(h1));
            hi[jp] = (uint32_t)__bfloat16_as_ushort(h0) | ((uint32_t)__bfloat16_as_ushort(h1) << 16);
            mi[jp] = (uint32_t)__bfloat16_as_ushort(m0) | ((uint32_t)__bfloat16_as_ushort(m1) << 16);
        }
        __nv_bfloat16* rowp = (which ? g_ks : g_qs)
                            + ((size_t)(b * NN + nb + n0 + i)) * 128 + o0;
        *(uint4*)(rowp)      = make_uint4(hi[0], hi[1], hi[2], hi[3]);
        *(uint4*)(rowp + 64) = make_uint4(mi[0], mi[1], mi[2], mi[3]);
    }
}

// ===========================================================================
// Attention, single pass (round-12 loop + round-6 rescale).
// CTA = 128 q-rows x 2048 cols, 256 thr = 8 warps:
//   warp = (rw 0..3: 32 rows = 2 m16 tiles, cg 0..1: 8 nt subtiles).
// B fragments once per (warp, nt) via ldmatrix.x4, reused for both row-tiles.
// 3 split-GEMMs {hh,hm,mh}; stores exp(e) raw + per-rowtile sums;
// then 1KB smem sum-merge and warp-local L2-hot rescale of own region.
// ===========================================================================
#define QROW  272
#define SQ    0
#define SK0   34816
#define SK1   69632
#define SSUM  104448                // 2*128 floats (cg halves)
#define SM_TOTAL 105472

__global__ __launch_bounds__(256, 1) void attention_kernel(float* __restrict__ att)
{
    extern __shared__ char smem[];
    const uint32_t sb = smem_u32(smem);
    const int t    = threadIdx.x;
    const int wid  = t >> 5;
    const int lane = t & 31;
    const int rw   = wid & 3;
    const int cg   = wid >> 2;
    const int nb   = blockIdx.x * 128;
    const int b    = blockIdx.y;
    const int r0   = rw * 32;

    {
        const char* ksrc = (const char*)(g_ks + ((size_t)(b * NN)) * 128);
        #pragma unroll
        for (int i = 0; i < 8; i++) {
            int id  = t + i * 256;
            int row = id >> 4, c16 = id & 15;
            CP_ASYNC16(sb + SK0 + row * QROW + c16 * 16, ksrc + row * 256 + c16 * 16);
        }
        CP_COMMIT();
        const char* qsrc = (const char*)(g_qs + ((size_t)(b * NN + nb)) * 128);
        #pragma unroll
        for (int i = 0; i < 8; i++) {
            int id  = t + i * 256;
            int row = id >> 4, c16 = id & 15;
            *(uint4*)(smem + SQ + row * QROW + c16 * 16) =
                *(const uint4*)(qsrc + row * 256 + c16 * 16);
        }
    }
    __syncthreads();

    // A fragments: a[comp][ks][rowtile][4]
    uint32_t a[2][4][2][4];
    #pragma unroll
    for (int rt = 0; rt < 2; rt++) {
        uint32_t qaddr = sb + SQ + (uint32_t)(r0 + rt * 16 + (lane & 15)) * QROW
                       + ((lane >> 4) & 1) * 16;
        #pragma unroll
        for (int c = 0; c < 2; c++)
            #pragma unroll
            for (int ks = 0; ks < 4; ks++)
                LDSM_X4(a[c][ks][rt][0], a[c][ks][rt][1], a[c][ks][rt][2], a[c][ks][rt][3],
                        qaddr + c * 128 + ks * 32);
    }

    // B x4 lane addressing: lanes 0-7 ks b0 | 8-15 ks b1 | 16-23 ks+1 b0 | 24-31 ks+1 b1
    const uint32_t kb4_lane = (uint32_t)((lane & 7) * QROW
                             + ((lane >> 3) & 1) * 16 + (lane >> 4) * 32);
    const int g = lane >> 2;
    const int cpair = (lane & 3) * 2;
    float s[2][2];
    s[0][0] = s[0][1] = s[1][0] = s[1][1] = 0.0f;
    float* rowp[2][2];
    #pragma unroll
    for (int rt = 0; rt < 2; rt++) {
        rowp[rt][0] = att + ((size_t)(b * NN + nb + r0 + rt * 16 + g)) * NN;
        rowp[rt][1] = rowp[rt][0] + 8 * NN;
    }

    for (int mt = 0; mt < 16; mt++) {
        if (mt + 1 < 16) {
            const char* ksrc = (const char*)(g_ks + ((size_t)(b * NN + (mt + 1) * 128)) * 128);
            uint32_t dst = sb + (((mt + 1) & 1) ? SK1 : SK0);
            #pragma unroll
            for (int i = 0; i < 8; i++) {
                int id  = t + i * 256;
                int row = id >> 4, c16 = id & 15;
                CP_ASYNC16(dst + row * QROW + c16 * 16, ksrc + row * 256 + c16 * 16);
            }
            CP_COMMIT();
            asm volatile("cp.async.wait_group 1;" ::: "memory");
        } else {
            asm volatile("cp.async.wait_group 0;" ::: "memory");
        }
        __syncthreads();

        const uint32_t kbase = sb + ((mt & 1) ? SK1 : SK0) + kb4_lane;
        const int mcol = mt * 128;

        #pragma unroll 4
        for (int nt8 = 0; nt8 < 8; nt8++) {
            const int nt = cg * 8 + nt8;
            uint32_t bb[2][4][2];
            uint32_t baddr = kbase + (uint32_t)nt * (8 * QROW);
            #pragma unroll
            for (int c = 0; c < 2; c++)
                #pragma unroll
                for (int ksp = 0; ksp < 2; ksp++)
                    LDSM_X4(bb[c][2*ksp][0], bb[c][2*ksp][1],
                            bb[c][2*ksp+1][0], bb[c][2*ksp+1][1],
                            baddr + c * 128 + ksp * 64);

            float hh[2][4] = {{0,0,0,0},{0,0,0,0}};
            float hm[2][4] = {{0,0,0,0},{0,0,0,0}};
            float mh[2][4] = {{0,0,0,0},{0,0,0,0}};
            #pragma unroll
            for (int ks = 0; ks < 4; ks++)
                #pragma unroll
                for (int rt = 0; rt < 2; rt++) {
                    mma_bf16(hh[rt][0], hh[rt][1], hh[rt][2], hh[rt][3],
                             a[0][ks][rt][0], a[0][ks][rt][1], a[0][ks][rt][2], a[0][ks][rt][3],
                             bb[0][ks][0], bb[0][ks][1]);
                    mma_bf16(hm[rt][0], hm[rt][1], hm[rt][2], hm[rt][3],
                             a[0][ks][rt][0], a[0][ks][rt][1], a[0][ks][rt][2], a[0][ks][rt][3],
                             bb[1][ks][0], bb[1][ks][1]);
                    mma_bf16(mh[rt][0], mh[rt][1], mh[rt][2], mh[rt][3],
                             a[1][ks][rt][0], a[1][ks][rt][1], a[1][ks][rt][2], a[1][ks][rt][3],
                             bb[0][ks][0], bb[0][ks][1]);
                }
            const int col = mcol + nt * 8 + cpair;
            #pragma unroll
            for (int rt = 0; rt < 2; rt++) {
                float c0 = (hh[rt][0] + hm[rt][0]) + mh[rt][0];
                float c1 = (hh[rt][1] + hm[rt][1]) + mh[rt][1];
                float c2 = (hh[rt][2] + hm[rt][2]) + mh[rt][2];
                float c3 = (hh[rt][3] + hm[rt][3]) + mh[rt][3];
                float e0 = __expf(c0), e1 = __expf(c1);
                float e2 = __expf(c2), e3 = __expf(c3);
                s[rt][0] += e0 + e1;
                s[rt][1] += e2 + e3;
                *(float2*)(rowp[rt][0] + col) = make_float2(e0, e1);
                *(float2*)(rowp[rt][1] + col) = make_float2(e2, e3);
            }
        }
        __syncthreads();
    }

    // quad-reduce partial sums, stash per-cg, merge
    float* sums = (float*)(smem + SSUM);
    #pragma unroll
    for (int rt = 0; rt < 2; rt++) {
        float lo = s[rt][0], hi = s[rt][1];
        lo += __shfl_xor_sync(0xffffffffu, lo, 1);
        lo += __shfl_xor_sync(0xffffffffu, lo, 2);
        hi += __shfl_xor_sync(0xffffffffu, hi, 1);
        hi += __shfl_xor_sync(0xffffffffu, hi, 2);
        if ((lane & 3) == 0) {
            sums[cg * 128 + r0 + rt * 16 + g]     = lo;
            sums[cg * 128 + r0 + rt * 16 + g + 8] = hi;
        }
    }
    __syncthreads();

    // rescale: warp-local RMW of exactly the region this warp wrote
    // (32 rows x its 64-col half of each of the 16 tiles), L2-hot
    for (int rr = 0; rr < 32; rr++) {
        const int row = r0 + rr;
        const float inv = 1.0f / (sums[row] + sums[128 + row]);
        float* rp = att + ((size_t)(b * NN + nb + row)) * NN + cg * 64;
        #pragma unroll
        for (int it = 0; it < 8; it++) {
            int c   = it * 32 + lane;        // 0..255
            int mtq = c >> 4;                // tile 0..15
            int off = (c & 15) * 4;          // 0..60 within the 64-col half
            float4* p = (float4*)(rp + mtq * 128 + off);
            float4 v = *p;
            v.x *= inv; v.y *= inv; v.z *= inv; v.w *= inv;
            *p = v;
        }
    }
}

// ---------------------------------------------------------------------------
// v projection (slow path, gamma != 0 only), internal loop over output chunk
// ---------------------------------------------------------------------------
__global__ __launch_bounds__(128) void v_kernel(
    const float* __restrict__ in, const float* __restrict__ W,
    const float* __restrict__ bias, const float* __restrict__ gate)
{
    if (gate[0] == 0.0f) return;
    const int t  = threadIdx.x;
    const int tx = t & 7;
    const int ty = t >> 3;
    const int n0 = tx * 8;
    const int o0 = ty * 4;
    const int nb = blockIdx.x * 64;
    const int b  = blockIdx.y;

    __shared__ float inT[32][68];
    __shared__ float wT [32][68];

    for (int obi = 0; obi < 8; obi++) {
        const int ob = obi * 64;
        float acc[4][8];
        #pragma unroll
        for (int o = 0; o < 4; o++)
            #pragma unroll
            for (int n = 0; n < 8; n++) acc[o][n] = 0.0f;

        for (int c0 = 0; c0 < CCH; c0 += 32) {
            __syncthreads();
            #pragma unroll
            for (int i = 0; i < 4; i++) {
                int l  = t + i * 128;
                int cc = l >> 4;
                int n4 = (l & 15) * 4;
                *(float4*)&inT[cc][n4] =
                    *(const float4*)&in[((b * CCH + c0 + cc) * NN) + nb + n4];
            }
            #pragma unroll
            for (int i = 0; i < 4; i++) {
                int l  = t + i * 128;
                int o  = l >> 3;
                int c4 = (l & 7) * 4;
                float4 w4 = *(const float4*)&W[(ob + o) * CCH + c0 + c4];
                wT[c4 + 0][o] = w4.x; wT[c4 + 1][o] = w4.y;
                wT[c4 + 2][o] = w4.z; wT[c4 + 3][o] = w4.w;
            }
            __syncthreads();
            #pragma unroll 8
            for (int cc = 0; cc < 32; cc++) {
                float4 wv = *(const float4*)&wT[cc][o0];
                float4 a0 = *(const float4*)&inT[cc][n0];
                float4 a1 = *(const float4*)&inT[cc][n0 + 4];
                float w[4] = {wv.x, wv.y, wv.z, wv.w};
                float v[8] = {a0.x, a0.y, a0.z, a0.w, a1.x, a1.y, a1.z, a1.w};
                #pragma unroll
                for (int o = 0; o < 4; o++)
                    #pragma unroll
                    for (int n = 0; n < 8; n++)
                        acc[o][n] = fmaf(w[o], v[n], acc[o][n]);
            }
        }

        #pragma unroll
        for (int o = 0; o < 4; o++) {
            int row = ob + o0 + o;
            float bb = bias[row];
            float* op = &g_v[((size_t)b * CCH + row) * NN + nb + n0];
            *(float4*)op       = make_float4(acc[o][0]+bb, acc[o][1]+bb, acc[o][2]+bb, acc[o][3]+bb);
            *(float4*)(op + 4) = make_float4(acc[o][4]+bb, acc[o][5]+bb, acc[o][6]+bb, acc[o][7]+bb);
        }
    }
}

// ---------------------------------------------------------------------------
// AV GEMM (slow path): writes out = gamma*(V@att^T) + x directly.
// ---------------------------------------------------------------------------
__global__ __launch_bounds__(128) void av_kernel(const float* __restrict__ att,
                                                 const float* __restrict__ x,
                                                 const float* __restrict__ gate,
                                                 float* __restrict__ out)
{
    const float gm = gate[0];
    if (gm == 0.0f) return;
    const int t  = threadIdx.x;
    const int tx = t & 7;
    const int ty = t >> 3;
    const int n0 = tx * 8;
    const int c0 = ty * 4;
    const int nb = blockIdx.x * 64;
    const int b  = blockIdx.y;

    __shared__ float vT[32][68];
    __shared__ float aT[32][68];

    for (int cbi = 0; cbi < 8; cbi++) {
        const int cb = cbi * 64;
        float acc[4][8];
        #pragma unroll
        for (int o = 0; o < 4; o++)
            #pragma unroll
            for (int n = 0; n < 8; n++) acc[o][n] = 0.0f;

        for (int mc = 0; mc < NN; mc += 32) {
            __syncthreads();
            #pragma unroll
            for (int i = 0; i < 4; i++) {
                int l  = t + i * 128;
                int c  = l >> 3;
                int m4 = (l & 7) * 4;
                float4 v = *(const float4*)&g_v[((size_t)b * CCH + cb + c) * NN + mc + m4];
                vT[m4 + 0][c] = v.x; vT[m4 + 1][c] = v.y;
                vT[m4 + 2][c] = v.z; vT[m4 + 3][c] = v.w;
                float4 aa = *(const float4*)&att[((size_t)(b * NN + nb + c)) * NN + mc + m4];
                aT[m4 + 0][c] = aa.x; aT[m4 + 1][c] = aa.y;
                aT[m4 + 2][c] = aa.z; aT[m4 + 3][c] = aa.w;
            }
            __syncthreads();
            #pragma unroll 8
            for (int mm = 0; mm < 32; mm++) {
                float4 vv = *(const float4*)&vT[mm][c0];
                float4 a0 = *(const float4*)&aT[mm][n0];
                float4 a1 = *(const float4*)&aT[mm][n0 + 4];
                float v[4] = {vv.x, vv.y, vv.z, vv.w};
                float aa[8] = {a0.x, a0.y, a0.z, a0.w, a1.x, a1.y, a1.z, a1.w};
                #pragma unroll
                for (int o = 0; o < 4; o++)
                    #pragma unroll
                    for (int n = 0; n < 8; n++)
                        acc[o][n] = fmaf(v[o], aa[n], acc[o][n]);
            }
        }

        #pragma unroll
        for (int o = 0; o < 4; o++) {
            size_t gidx = ((size_t)b * CCH + cb + c0 + o) * NN + nb + n0;
            float4 x0 = *(const float4*)&x[gidx];
            float4 x1 = *(const float4*)&x[gidx + 4];
            *(float4*)&out[gidx] = make_float4(
                fmaf(gm, acc[o][0], x0.x), fmaf(gm, acc[o][1], x0.y),
                fmaf(gm, acc[o][2], x0.z), fmaf(gm, acc[o][3], x0.w));
            *(float4*)&out[gidx + 4] = make_float4(
                fmaf(gm, acc[o][4], x1.x), fmaf(gm, acc[o][5], x1.y),
                fmaf(gm, acc[o][6], x1.z), fmaf(gm, acc[o][7], x1.w));
        }
    }
}

// ---------------------------------------------------------------------------
extern "C" void kernel_launch(void* const* d_in, const int* in_sizes, int n_in,
                              void* d_out, int out_size)
{
    (void)in_sizes; (void)n_in; (void)out_size;
    const float* x     = (const float*)d_in[0];
    const float* y     = (const float*)d_in[1];
    const float* Wq    = (const float*)d_in[2];
    const float* bq    = (const float*)d_in[3];
    const float* Wk    = (const float*)d_in[4];
    const float* bk    = (const float*)d_in[5];
    const float* Wv    = (const float*)d_in[6];
    const float* bv    = (const float*)d_in[7];
    const float* gamma = (const float*)d_in[8];

    float* out = (float*)d_out;
    float* att = out + OUT_OFF;

    cudaFuncSetAttribute(attention_kernel,
                         cudaFuncAttributeMaxDynamicSharedMemorySize, SM_TOTAL);

    // idx 0: q = Wq*y+bq, k = Wk*x+bk (merged; which==1 writes out = x)
    qk_kernel<<<dim3(NN/128, BB, 2), 128>>>(x, y, Wq, bq, Wk, bk, out);
    // idx 1: v projection (gated)
    v_kernel<<<dim3(NN/64, BB), 128>>>(y, Wv, bv, gamma);
    // idx 2: attention single pass (store exp + L2-hot rescale)
    attention_kernel<<<dim3(16, BB), 256, SM_TOTAL>>>(att);
    // idx 3: out = gamma*(V@att^T) + x (gated)
    av_kernel<<<dim3(NN/64, BB), 128>>>(att, x, gamma, out);
}

// round 14
// speedup vs baseline: 1.4669x; 1.4669x over previous
#include <cuda_runtime.h>
#include <cuda_bf16.h>
#include <math.h>
#include <cstdint>

// Problem constants
#define BB   8
#define CCH  512
#define C8   64
#define NN   2048
#define OUT_OFF (BB*CCH*NN)   // start of attention region in d_out (floats)

typedef unsigned long long u64;

// Scratch: q/k as 2-way bf16 split [b][n][comp*64 + o], comp 0=hi, 1=mid
__device__ __nv_bfloat16 g_qs[BB*NN*128];
__device__ __nv_bfloat16 g_ks[BB*NN*128];
__device__ float g_inv[BB*NN];             // per-row 1/sum(exp(e))
__device__ float g_v[BB*CCH*NN];           // slow path only (gamma != 0)

// ---- packed f32x2 helpers ------------------------------------------------
__device__ __forceinline__ u64 pack2(float x) {
    u64 r; asm("mov.b64 %0, {%1, %1};" : "=l"(r) : "f"(x)); return r;
}
__device__ __forceinline__ void ffma2(u64& d, u64 a, u64 b) {
    asm("fma.rn.f32x2 %0, %1, %2, %3;" : "=l"(d) : "l"(a), "l"(b), "l"(d));
}
__device__ __forceinline__ float2 unpack2(u64 v) {
    float2 f; asm("mov.b64 {%0, %1}, %2;" : "=f"(f.x), "=f"(f.y) : "l"(v)); return f;
}

// ---- sm_80-class tensor helpers (legal on plain sm_103 target) -----------
__device__ __forceinline__ uint32_t smem_u32(const void* p) {
    uint32_t a;
    asm("{ .reg .u64 t; cvta.to.shared.u64 t, %1; cvt.u32.u64 %0, t; }" : "=r"(a) : "l"(p));
    return a;
}
#define LDSM_X4(r0, r1, r2, r3, addr) \
    asm volatile("ldmatrix.sync.aligned.m8n8.x4.shared.b16 {%0,%1,%2,%3}, [%4];" \
        : "=r"(r0), "=r"(r1), "=r"(r2), "=r"(r3) : "r"(addr))
#define CP_ASYNC16(dst, src) \
    asm volatile("cp.async.cg.shared.global [%0], [%1], 16;" :: "r"(dst), "l"(src) : "memory")
#define CP_COMMIT() asm volatile("cp.async.commit_group;" ::: "memory")

__device__ __forceinline__ void mma_bf16(float& c0, float& c1, float& c2, float& c3,
                                         uint32_t a0, uint32_t a1, uint32_t a2, uint32_t a3,
                                         uint32_t b0, uint32_t b1) {
    asm volatile(
        "mma.sync.aligned.m16n8k16.row.col.f32.bf16.bf16.f32 "
        "{%0,%1,%2,%3}, {%4,%5,%6,%7}, {%8,%9}, {%0,%1,%2,%3};"
        : "+f"(c0), "+f"(c1), "+f"(c2), "+f"(c3)
        : "r"(a0), "r"(a1), "r"(a2), "r"(a3), "r"(b0), "r"(b1));
}

// ---------------------------------------------------------------------------
// Fused q+k projection (FFMA2) -> 2-way bf16 split, layout [b][n][comp*64+o].
// which==1 (k from x) additionally copies x into out region (out = x).
// ---------------------------------------------------------------------------
__global__ __launch_bounds__(128, 3) void qk_kernel(
    const float* __restrict__ x, const float* __restrict__ y,
    const float* __restrict__ Wq, const float* __restrict__ bq,
    const float* __restrict__ Wk, const float* __restrict__ bk,
    float* __restrict__ outx)
{
    const int which = blockIdx.z;
    const float* in   = which ? x  : y;
    const float* W    = which ? Wk : Wq;
    const float* bias = which ? bk : bq;

    const int t  = threadIdx.x;
    const int tx = t & 15;
    const int ty = t >> 4;
    const int n0 = tx * 8;
    const int o0 = ty * 8;
    const int nb = blockIdx.x * 128;
    const int b  = blockIdx.y;

    __shared__ float wt[32][68];
    __shared__ float it[32][128];

    u64 acc[8][4];
    #pragma unroll
    for (int j = 0; j < 8; j++)
        #pragma unroll
        for (int i = 0; i < 4; i++) acc[j][i] = 0ull;

    for (int c0 = 0; c0 < CCH; c0 += 32) {
        __syncthreads();
        #pragma unroll
        for (int i = 0; i < 4; i++) {
            int l  = t + i * 128;
            int o  = l >> 3;
            int c4 = (l & 7) * 4;
            float4 w4 = *(const float4*)&W[o * CCH + c0 + c4];
            wt[c4 + 0][o] = w4.x; wt[c4 + 1][o] = w4.y;
            wt[c4 + 2][o] = w4.z; wt[c4 + 3][o] = w4.w;
        }
        #pragma unroll
        for (int i = 0; i < 8; i++) {
            int l  = t + i * 128;
            int cc = l >> 5;
            int n4 = (l & 31) * 4;
            size_t gidx = ((size_t)(b * CCH + c0 + cc) * NN) + nb + n4;
            float4 v = *(const float4*)&in[gidx];
            *(float4*)&it[cc][n4] = v;
            if (which) *(float4*)&outx[gidx] = v;   // out = x (residual copy)
        }
        __syncthreads();

        #pragma unroll 4
        for (int cc = 0; cc < 32; cc++) {
            float4 w0 = *(const float4*)&wt[cc][o0];
            float4 w1 = *(const float4*)&wt[cc][o0 + 4];
            u64 wp[8] = {pack2(w0.x), pack2(w0.y), pack2(w0.z), pack2(w0.w),
                         pack2(w1.x), pack2(w1.y), pack2(w1.z), pack2(w1.w)};
            ulonglong2 ia = *(const ulonglong2*)&it[cc][n0];
            ulonglong2 ib = *(const ulonglong2*)&it[cc][n0 + 4];
            u64 iv[4] = {ia.x, ia.y, ib.x, ib.y};
            #pragma unroll
            for (int j = 0; j < 8; j++)
                #pragma unroll
                for (int i = 0; i < 4; i++)
                    ffma2(acc[j][i], wp[j], iv[i]);
        }
    }

    float val[8][8];
    #pragma unroll
    for (int j = 0; j < 8; j++) {
        float bb = bias[o0 + j];
        float2 p0 = unpack2(acc[j][0]);
        float2 p1 = unpack2(acc[j][1]);
        float2 p2 = unpack2(acc[j][2]);
        float2 p3 = unpack2(acc[j][3]);
        val[j][0] = p0.x + bb; val[j][1] = p0.y + bb;
        val[j][2] = p1.x + bb; val[j][3] = p1.y + bb;
        val[j][4] = p2.x + bb; val[j][5] = p2.y + bb;
        val[j][6] = p3.x + bb; val[j][7] = p3.y + bb;
    }

    #pragma unroll
    for (int i = 0; i < 8; i++) {
        uint32_t hi[4], mi[4];
        #pragma unroll
        for (int jp = 0; jp < 4; jp++) {
            float v0 = val[2*jp][i], v1 = val[2*jp+1][i];
            __nv_bfloat16 h0 = __float2bfloat16(v0);
            __nv_bfloat16 m0 = __float2bfloat16(v0 - __bfloat162float(h0));
            __nv_bfloat16 h1 = __float2bfloat16(v1);
            __nv_bfloat16 m1 = __float2bfloat16(v1 - __bfloat162float(h1));
            hi[jp] = (uint32_t)__bfloat16_as_ushort(h0) | ((uint32_t)__bfloat16_as_ushort(h1) << 16);
            mi[jp] = (uint32_t)__bfloat16_as_ushort(m0) | ((uint32_t)__bfloat16_as_ushort(m1) << 16);
        }
        __nv_bfloat16* rowp = (which ? g_ks : g_qs)
                            + ((size_t)(b * NN + nb + n0 + i)) * 128 + o0;
        *(uint4*)(rowp)      = make_uint4(hi[0], hi[1], hi[2], hi[3]);
        *(uint4*)(rowp + 64) = make_uint4(mi[0], mi[1], mi[2], mi[3]);
    }
}

// ===========================================================================
// Attention (round-12 loop): stores RAW exp(e), accumulates row sums,
// writes g_inv.  Normalization done by the separate rescale_kernel.
// CTA = 128 q-rows x 2048 cols, 256 thr = 8 warps:
//   warp = (rw 0..3: 32 rows = 2 m16 tiles, cg 0..1: 8 nt subtiles).
// ===========================================================================
#define QROW  272
#define SQ    0
#define SK0   34816
#define SK1   69632
#define SSUM  104448                // 2*128 floats (cg halves)
#define SM_TOTAL 105472

__global__ __launch_bounds__(256, 1) void attention_kernel(float* __restrict__ att)
{
    extern __shared__ char smem[];
    const uint32_t sb = smem_u32(smem);
    const int t    = threadIdx.x;
    const int wid  = t >> 5;
    const int lane = t & 31;
    const int rw   = wid & 3;
    const int cg   = wid >> 2;
    const int nb   = blockIdx.x * 128;
    const int b    = blockIdx.y;
    const int r0   = rw * 32;

    {
        const char* ksrc = (const char*)(g_ks + ((size_t)(b * NN)) * 128);
        #pragma unroll
        for (int i = 0; i < 8; i++) {
            int id  = t + i * 256;
            int row = id >> 4, c16 = id & 15;
            CP_ASYNC16(sb + SK0 + row * QROW + c16 * 16, ksrc + row * 256 + c16 * 16);
        }
        CP_COMMIT();
        const char* qsrc = (const char*)(g_qs + ((size_t)(b * NN + nb)) * 128);
        #pragma unroll
        for (int i = 0; i < 8; i++) {
            int id  = t + i * 256;
            int row = id >> 4, c16 = id & 15;
            *(uint4*)(smem + SQ + row * QROW + c16 * 16) =
                *(const uint4*)(qsrc + row * 256 + c16 * 16);
        }
    }
    __syncthreads();

    // A fragments: a[comp][ks][rowtile][4]
    uint32_t a[2][4][2][4];
    #pragma unroll
    for (int rt = 0; rt < 2; rt++) {
        uint32_t qaddr = sb + SQ + (uint32_t)(r0 + rt * 16 + (lane & 15)) * QROW
                       + ((lane >> 4) & 1) * 16;
        #pragma unroll
        for (int c = 0; c < 2; c++)
            #pragma unroll
            for (int ks = 0; ks < 4; ks++)
                LDSM_X4(a[c][ks][rt][0], a[c][ks][rt][1], a[c][ks][rt][2], a[c][ks][rt][3],
                        qaddr + c * 128 + ks * 32);
    }

    const uint32_t kb4_lane = (uint32_t)((lane & 7) * QROW
                             + ((lane >> 3) & 1) * 16 + (lane >> 4) * 32);
    const int g = lane >> 2;
    const int cpair = (lane & 3) * 2;
    float s[2][2];
    s[0][0] = s[0][1] = s[1][0] = s[1][1] = 0.0f;
    float* rowp[2][2];
    #pragma unroll
    for (int rt = 0; rt < 2; rt++) {
        rowp[rt][0] = att + ((size_t)(b * NN + nb + r0 + rt * 16 + g)) * NN;
        rowp[rt][1] = rowp[rt][0] + 8 * NN;
    }

    for (int mt = 0; mt < 16; mt++) {
        if (mt + 1 < 16) {
            const char* ksrc = (const char*)(g_ks + ((size_t)(b * NN + (mt + 1) * 128)) * 128);
            uint32_t dst = sb + (((mt + 1) & 1) ? SK1 : SK0);
            #pragma unroll
            for (int i = 0; i < 8; i++) {
                int id  = t + i * 256;
                int row = id >> 4, c16 = id & 15;
                CP_ASYNC16(dst + row * QROW + c16 * 16, ksrc + row * 256 + c16 * 16);
            }
            CP_COMMIT();
            asm volatile("cp.async.wait_group 1;" ::: "memory");
        } else {
            asm volatile("cp.async.wait_group 0;" ::: "memory");
        }
        __syncthreads();

        const uint32_t kbase = sb + ((mt & 1) ? SK1 : SK0) + kb4_lane;
        const int mcol = mt * 128;

        #pragma unroll 4
        for (int nt8 = 0; nt8 < 8; nt8++) {
            const int nt = cg * 8 + nt8;
            uint32_t bb[2][4][2];
            uint32_t baddr = kbase + (uint32_t)nt * (8 * QROW);
            #pragma unroll
            for (int c = 0; c < 2; c++)
                #pragma unroll
                for (int ksp = 0; ksp < 2; ksp++)
                    LDSM_X4(bb[c][2*ksp][0], bb[c][2*ksp][1],
                            bb[c][2*ksp+1][0], bb[c][2*ksp+1][1],
                            baddr + c * 128 + ksp * 64);

            float hh[2][4] = {{0,0,0,0},{0,0,0,0}};
            float hm[2][4] = {{0,0,0,0},{0,0,0,0}};
            float mh[2][4] = {{0,0,0,0},{0,0,0,0}};
            #pragma unroll
            for (int ks = 0; ks < 4; ks++)
                #pragma unroll
                for (int rt = 0; rt < 2; rt++) {
                    mma_bf16(hh[rt][0], hh[rt][1], hh[rt][2], hh[rt][3],
                             a[0][ks][rt][0], a[0][ks][rt][1], a[0][ks][rt][2], a[0][ks][rt][3],
                             bb[0][ks][0], bb[0][ks][1]);
                    mma_bf16(hm[rt][0], hm[rt][1], hm[rt][2], hm[rt][3],
                             a[0][ks][rt][0], a[0][ks][rt][1], a[0][ks][rt][2], a[0][ks][rt][3],
                             bb[1][ks][0], bb[1][ks][1]);
                    mma_bf16(mh[rt][0], mh[rt][1], mh[rt][2], mh[rt][3],
                             a[1][ks][rt][0], a[1][ks][rt][1], a[1][ks][rt][2], a[1][ks][rt][3],
                             bb[0][ks][0], bb[0][ks][1]);
                }
            const int col = mcol + nt * 8 + cpair;
            #pragma unroll
            for (int rt = 0; rt < 2; rt++) {
                float c0 = (hh[rt][0] + hm[rt][0]) + mh[rt][0];
                float c1 = (hh[rt][1] + hm[rt][1]) + mh[rt][1];
                float c2 = (hh[rt][2] + hm[rt][2]) + mh[rt][2];
                float c3 = (hh[rt][3] + hm[rt][3]) + mh[rt][3];
                float e0 = __expf(c0), e1 = __expf(c1);
                float e2 = __expf(c2), e3 = __expf(c3);
                s[rt][0] += e0 + e1;
                s[rt][1] += e2 + e3;
                *(float2*)(rowp[rt][0] + col) = make_float2(e0, e1);
                *(float2*)(rowp[rt][1] + col) = make_float2(e2, e3);
            }
        }
        __syncthreads();
    }

    // quad-reduce partial sums, stash per-cg, merge -> g_inv
    float* sums = (float*)(smem + SSUM);
    #pragma unroll
    for (int rt = 0; rt < 2; rt++) {
        float lo = s[rt][0], hi = s[rt][1];
        lo += __shfl_xor_sync(0xffffffffu, lo, 1);
        lo += __shfl_xor_sync(0xffffffffu, lo, 2);
        hi += __shfl_xor_sync(0xffffffffu, hi, 1);
        hi += __shfl_xor_sync(0xffffffffu, hi, 2);
        if ((lane & 3) == 0) {
            sums[cg * 128 + r0 + rt * 16 + g]     = lo;
            sums[cg * 128 + r0 + rt * 16 + g + 8] = hi;
        }
    }
    __syncthreads();
    if (t < 128)
        g_inv[b * NN + nb + t] = 1.0f / (sums[t] + sums[128 + t]);
}

// ---------------------------------------------------------------------------
// Rescale: att[b][row][*] *= g_inv[b][row].  Full-occupancy coalesced RMW.
// ---------------------------------------------------------------------------
__global__ __launch_bounds__(256) void rescale_kernel(float* __restrict__ att)
{
    const int row = blockIdx.x;
    const int b   = blockIdx.y;
    const float inv = g_inv[b * NN + row];
    float4* p = (float4*)(att + ((size_t)(b * NN + row)) * NN);
    const int t = threadIdx.x;
    #pragma unroll
    for (int i = 0; i < 2; i++) {
        float4 v = p[t + i * 256];
        v.x *= inv; v.y *= inv; v.z *= inv; v.w *= inv;
        p[t + i * 256] = v;
    }
}

// ---------------------------------------------------------------------------
// v projection (slow path, gamma != 0 only); grid 64 CTAs, internal loops
// ---------------------------------------------------------------------------
__global__ __launch_bounds__(128) void v_kernel(
    const float* __restrict__ in, const float* __restrict__ W,
    const float* __restrict__ bias, const float* __restrict__ gate)
{
    if (gate[0] == 0.0f) return;
    const int t  = threadIdx.x;
    const int tx = t & 7;
    const int ty = t >> 3;
    const int n0 = tx * 8;
    const int o0 = ty * 4;
    const int b  = blockIdx.y;

    __shared__ float inT[32][68];
    __shared__ float wT [32][68];

    for (int nbi = 0; nbi < 4; nbi++) {
        const int nb = (blockIdx.x * 4 + nbi) * 64;
        for (int obi = 0; obi < 8; obi++) {
            const int ob = obi * 64;
            float acc[4][8];
            #pragma unroll
            for (int o = 0; o < 4; o++)
                #pragma unroll
                for (int n = 0; n < 8; n++) acc[o][n] = 0.0f;

            for (int c0 = 0; c0 < CCH; c0 += 32) {
                __syncthreads();
                #pragma unroll
                for (int i = 0; i < 4; i++) {
                    int l  = t + i * 128;
                    int cc = l >> 4;
                    int n4 = (l & 15) * 4;
                    *(float4*)&inT[cc][n4] =
                        *(const float4*)&in[((b * CCH + c0 + cc) * NN) + nb + n4];
                }
                #pragma unroll
                for (int i = 0; i < 4; i++) {
                    int l  = t + i * 128;
                    int o  = l >> 3;
                    int c4 = (l & 7) * 4;
                    float4 w4 = *(const float4*)&W[(ob + o) * CCH + c0 + c4];
                    wT[c4 + 0][o] = w4.x; wT[c4 + 1][o] = w4.y;
                    wT[c4 + 2][o] = w4.z; wT[c4 + 3][o] = w4.w;
                }
                __syncthreads();
                #pragma unroll 8
                for (int cc = 0; cc < 32; cc++) {
                    float4 wv = *(const float4*)&wT[cc][o0];
                    float4 a0 = *(const float4*)&inT[cc][n0];
                    float4 a1 = *(const float4*)&inT[cc][n0 + 4];
                    float w[4] = {wv.x, wv.y, wv.z, wv.w};
                    float v[8] = {a0.x, a0.y, a0.z, a0.w, a1.x, a1.y, a1.z, a1.w};
                    #pragma unroll
                    for (int o = 0; o < 4; o++)
                        #pragma unroll
                        for (int n = 0; n < 8; n++)
                            acc[o][n] = fmaf(w[o], v[n], acc[o][n]);
                }
            }

            #pragma unroll
            for (int o = 0; o < 4; o++) {
                int row = ob + o0 + o;
                float bb = bias[row];
                float* op = &g_v[((size_t)b * CCH + row) * NN + nb + n0];
                *(float4*)op       = make_float4(acc[o][0]+bb, acc[o][1]+bb, acc[o][2]+bb, acc[o][3]+bb);
                *(float4*)(op + 4) = make_float4(acc[o][4]+bb, acc[o][5]+bb, acc[o][6]+bb, acc[o][7]+bb);
            }
        }
    }
}

// ---------------------------------------------------------------------------
// AV GEMM (slow path): out = gamma*(V@att^T) + x; grid 64 CTAs, internal loops
// ---------------------------------------------------------------------------
__global__ __launch_bounds__(128) void av_kernel(const float* __restrict__ att,
                                                 const float* __restrict__ x,
                                                 const float* __restrict__ gate,
                                                 float* __restrict__ out)
{
    const float gm = gate[0];
    if (gm == 0.0f) return;
    const int t  = threadIdx.x;
    const int tx = t & 7;
    const int ty = t >> 3;
    const int n0 = tx * 8;
    const int c0 = ty * 4;
    const int b  = blockIdx.y;

    __shared__ float vT[32][68];
    __shared__ float aT[32][68];

    for (int nbi = 0; nbi < 4; nbi++) {
        const int nb = (blockIdx.x * 4 + nbi) * 64;
        for (int cbi = 0; cbi < 8; cbi++) {
            const int cb = cbi * 64;
            float acc[4][8];
            #pragma unroll
            for (int o = 0; o < 4; o++)
                #pragma unroll
                for (int n = 0; n < 8; n++) acc[o][n] = 0.0f;

            for (int mc = 0; mc < NN; mc += 32) {
                __syncthreads();
                #pragma unroll
                for (int i = 0; i < 4; i++) {
                    int l  = t + i * 128;
                    int c  = l >> 3;
                    int m4 = (l & 7) * 4;
                    float4 v = *(const float4*)&g_v[((size_t)b * CCH + cb + c) * NN + mc + m4];
                    vT[m4 + 0][c] = v.x; vT[m4 + 1][c] = v.y;
                    vT[m4 + 2][c] = v.z; vT[m4 + 3][c] = v.w;
                    float4 aa = *(const float4*)&att[((size_t)(b * NN + nb + c)) * NN + mc + m4];
                    aT[m4 + 0][c] = aa.x; aT[m4 + 1][c] = aa.y;
                    aT[m4 + 2][c] = aa.z; aT[m4 + 3][c] = aa.w;
                }
                __syncthreads();
                #pragma unroll 8
                for (int mm = 0; mm < 32; mm++) {
                    float4 vv = *(const float4*)&vT[mm][c0];
                    float4 a0 = *(const float4*)&aT[mm][n0];
                    float4 a1 = *(const float4*)&aT[mm][n0 + 4];
                    float v[4] = {vv.x, vv.y, vv.z, vv.w};
                    float aa[8] = {a0.x, a0.y, a0.z, a0.w, a1.x, a1.y, a1.z, a1.w};
                    #pragma unroll
                    for (int o = 0; o < 4; o++)
                        #pragma unroll
                        for (int n = 0; n < 8; n++)
                            acc[o][n] = fmaf(v[o], aa[n], acc[o][n]);
                }
            }

            #pragma unroll
            for (int o = 0; o < 4; o++) {
                size_t gidx = ((size_t)b * CCH + cb + c0 + o) * NN + nb + n0;
                float4 x0 = *(const float4*)&x[gidx];
                float4 x1 = *(const float4*)&x[gidx + 4];
                *(float4*)&out[gidx] = make_float4(
                    fmaf(gm, acc[o][0], x0.x), fmaf(gm, acc[o][1], x0.y),
                    fmaf(gm, acc[o][2], x0.z), fmaf(gm, acc[o][3], x0.w));
                *(float4*)&out[gidx + 4] = make_float4(
                    fmaf(gm, acc[o][4], x1.x), fmaf(gm, acc[o][5], x1.y),
                    fmaf(gm, acc[o][6], x1.z), fmaf(gm, acc[o][7], x1.w));
            }
        }
    }
}

// ---------------------------------------------------------------------------
extern "C" void kernel_launch(void* const* d_in, const int* in_sizes, int n_in,
                              void* d_out, int out_size)
{
    (void)in_sizes; (void)n_in; (void)out_size;
    const float* x     = (const float*)d_in[0];
    const float* y     = (const float*)d_in[1];
    const float* Wq    = (const float*)d_in[2];
    const float* bq    = (const float*)d_in[3];
    const float* Wk    = (const float*)d_in[4];
    const float* bk    = (const float*)d_in[5];
    const float* Wv    = (const float*)d_in[6];
    const float* bv    = (const float*)d_in[7];
    const float* gamma = (const float*)d_in[8];

    float* out = (float*)d_out;
    float* att = out + OUT_OFF;

    cudaFuncSetAttribute(attention_kernel,
                         cudaFuncAttributeMaxDynamicSharedMemorySize, SM_TOTAL);

    // idx 0: q = Wq*y+bq, k = Wk*x+bk (merged; which==1 writes out = x)
    qk_kernel<<<dim3(NN/128, BB, 2), 128>>>(x, y, Wq, bq, Wk, bk, out);
    // idx 1: v projection (gated, 64 CTAs)
    v_kernel<<<dim3(8, BB), 128>>>(y, Wv, bv, gamma);
    // idx 2: attention — raw exp(e) + row sums -> g_inv
    attention_kernel<<<dim3(16, BB), 256, SM_TOTAL>>>(att);
    // idx 3: rescale att by 1/S (ncu capture slot)
    rescale_kernel<<<dim3(NN, BB), 256>>>(att);
    // idx 4: out = gamma*(V@att^T) + x (gated, 64 CTAs)
    av_kernel<<<dim3(8, BB), 128>>>(att, x, gamma, out);
}

// round 15
// speedup vs baseline: 1.5050x; 1.0259x over previous
#include <cuda_runtime.h>
#include <cuda_bf16.h>
#include <math.h>
#include <cstdint>

// Problem constants
#define BB   8
#define CCH  512
#define C8   64
#define NN   2048
#define OUT_OFF (BB*CCH*NN)   // start of attention region in d_out (floats)

typedef unsigned long long u64;

// Scratch: q/k as 2-way bf16 split [b][n][comp*64 + o], comp 0=hi, 1=mid
__device__ __nv_bfloat16 g_qs[BB*NN*128];
__device__ __nv_bfloat16 g_ks[BB*NN*128];
__device__ float g_inv[BB*NN];             // per-row 1/sum(exp(e))
__device__ float g_v[BB*CCH*NN];           // slow path only (gamma != 0)

// ---- packed f32x2 helpers ------------------------------------------------
__device__ __forceinline__ u64 pack2(float x) {
    u64 r; asm("mov.b64 %0, {%1, %1};" : "=l"(r) : "f"(x)); return r;
}
__device__ __forceinline__ void ffma2(u64& d, u64 a, u64 b) {
    asm("fma.rn.f32x2 %0, %1, %2, %3;" : "=l"(d) : "l"(a), "l"(b), "l"(d));
}
__device__ __forceinline__ float2 unpack2(u64 v) {
    float2 f; asm("mov.b64 {%0, %1}, %2;" : "=f"(f.x), "=f"(f.y) : "l"(v)); return f;
}

// ---- sm_80-class tensor helpers (legal on plain sm_103 target) -----------
__device__ __forceinline__ uint32_t smem_u32(const void* p) {
    uint32_t a;
    asm("{ .reg .u64 t; cvta.to.shared.u64 t, %1; cvt.u32.u64 %0, t; }" : "=r"(a) : "l"(p));
    return a;
}
#define LDSM_X4(r0, r1, r2, r3, addr) \
    asm volatile("ldmatrix.sync.aligned.m8n8.x4.shared.b16 {%0,%1,%2,%3}, [%4];" \
        : "=r"(r0), "=r"(r1), "=r"(r2), "=r"(r3) : "r"(addr))
#define CP_ASYNC16(dst, src) \
    asm volatile("cp.async.cg.shared.global [%0], [%1], 16;" :: "r"(dst), "l"(src) : "memory")
#define CP_COMMIT() asm volatile("cp.async.commit_group;" ::: "memory")

__device__ __forceinline__ void mma_bf16(float& c0, float& c1, float& c2, float& c3,
                                         uint32_t a0, uint32_t a1, uint32_t a2, uint32_t a3,
                                         uint32_t b0, uint32_t b1) {
    asm volatile(
        "mma.sync.aligned.m16n8k16.row.col.f32.bf16.bf16.f32 "
        "{%0,%1,%2,%3}, {%4,%5,%6,%7}, {%8,%9}, {%0,%1,%2,%3};"
        : "+f"(c0), "+f"(c1), "+f"(c2), "+f"(c3)
        : "r"(a0), "r"(a1), "r"(a2), "r"(a3), "r"(b0), "r"(b1));
}

// ---------------------------------------------------------------------------
// Fused q/k/v projections in one launch.
//   z=0: q = Wq*y+bq   z=1: k = Wk*x+bk (+ out = x copy)   z=2: v (gated)
// q/k: FFMA2 -> 2-way bf16 split, layout [b][n][comp*64+o].
// ---------------------------------------------------------------------------
__global__ __launch_bounds__(128, 3) void qkv_kernel(
    const float* __restrict__ x, const float* __restrict__ y,
    const float* __restrict__ Wq, const float* __restrict__ bq,
    const float* __restrict__ Wk, const float* __restrict__ bk,
    const float* __restrict__ Wv, const float* __restrict__ bv,
    const float* __restrict__ gamma, float* __restrict__ outx)
{
    __shared__ float wt[32][68];
    __shared__ float it[32][128];
    __shared__ float inT[32][68];
    __shared__ float wT [32][68];

    const int which = blockIdx.z;
    const int t  = threadIdx.x;
    const int b  = blockIdx.y;

    if (which == 2) {
        // ---- v projection (gated on gamma != 0) ----
        if (gamma[0] == 0.0f) return;
        const int tx = t & 7;
        const int ty = t >> 3;
        const int n0 = tx * 8;
        const int o0 = ty * 4;

        for (int nbi = 0; nbi < 2; nbi++) {
            const int nb = blockIdx.x * 128 + nbi * 64;
            for (int obi = 0; obi < 8; obi++) {
                const int ob = obi * 64;
                float acc[4][8];
                #pragma unroll
                for (int o = 0; o < 4; o++)
                    #pragma unroll
                    for (int n = 0; n < 8; n++) acc[o][n] = 0.0f;

                for (int c0 = 0; c0 < CCH; c0 += 32) {
                    __syncthreads();
                    #pragma unroll
                    for (int i = 0; i < 4; i++) {
                        int l  = t + i * 128;
                        int cc = l >> 4;
                        int n4 = (l & 15) * 4;
                        *(float4*)&inT[cc][n4] =
                            *(const float4*)&y[((b * CCH + c0 + cc) * NN) + nb + n4];
                    }
                    #pragma unroll
                    for (int i = 0; i < 4; i++) {
                        int l  = t + i * 128;
                        int o  = l >> 3;
                        int c4 = (l & 7) * 4;
                        float4 w4 = *(const float4*)&Wv[(ob + o) * CCH + c0 + c4];
                        wT[c4 + 0][o] = w4.x; wT[c4 + 1][o] = w4.y;
                        wT[c4 + 2][o] = w4.z; wT[c4 + 3][o] = w4.w;
                    }
                    __syncthreads();
                    #pragma unroll 8
                    for (int cc = 0; cc < 32; cc++) {
                        float4 wv = *(const float4*)&wT[cc][o0];
                        float4 a0 = *(const float4*)&inT[cc][n0];
                        float4 a1 = *(const float4*)&inT[cc][n0 + 4];
                        float w[4] = {wv.x, wv.y, wv.z, wv.w};
                        float v[8] = {a0.x, a0.y, a0.z, a0.w, a1.x, a1.y, a1.z, a1.w};
                        #pragma unroll
                        for (int o = 0; o < 4; o++)
                            #pragma unroll
                            for (int n = 0; n < 8; n++)
                                acc[o][n] = fmaf(w[o], v[n], acc[o][n]);
                    }
                }

                #pragma unroll
                for (int o = 0; o < 4; o++) {
                    int row = ob + o0 + o;
                    float bb = bv[row];
                    float* op = &g_v[((size_t)b * CCH + row) * NN + nb + n0];
                    *(float4*)op       = make_float4(acc[o][0]+bb, acc[o][1]+bb, acc[o][2]+bb, acc[o][3]+bb);
                    *(float4*)(op + 4) = make_float4(acc[o][4]+bb, acc[o][5]+bb, acc[o][6]+bb, acc[o][7]+bb);
                }
            }
        }
        return;
    }

    // ---- q/k projection (FFMA2, bf16 split) ----
    const float* in   = which ? x  : y;
    const float* W    = which ? Wk : Wq;
    const float* bias = which ? bk : bq;

    const int tx = t & 15;
    const int ty = t >> 4;
    const int n0 = tx * 8;
    const int o0 = ty * 8;
    const int nb = blockIdx.x * 128;

    u64 acc[8][4];
    #pragma unroll
    for (int j = 0; j < 8; j++)
        #pragma unroll
        for (int i = 0; i < 4; i++) acc[j][i] = 0ull;

    for (int c0 = 0; c0 < CCH; c0 += 32) {
        __syncthreads();
        #pragma unroll
        for (int i = 0; i < 4; i++) {
            int l  = t + i * 128;
            int o  = l >> 3;
            int c4 = (l & 7) * 4;
            float4 w4 = *(const float4*)&W[o * CCH + c0 + c4];
            wt[c4 + 0][o] = w4.x; wt[c4 + 1][o] = w4.y;
            wt[c4 + 2][o] = w4.z; wt[c4 + 3][o] = w4.w;
        }
        #pragma unroll
        for (int i = 0; i < 8; i++) {
            int l  = t + i * 128;
            int cc = l >> 5;
            int n4 = (l & 31) * 4;
            size_t gidx = ((size_t)(b * CCH + c0 + cc) * NN) + nb + n4;
            float4 v = *(const float4*)&in[gidx];
            *(float4*)&it[cc][n4] = v;
            if (which) *(float4*)&outx[gidx] = v;   // out = x (residual copy)
        }
        __syncthreads();

        #pragma unroll 4
        for (int cc = 0; cc < 32; cc++) {
            float4 w0 = *(const float4*)&wt[cc][o0];
            float4 w1 = *(const float4*)&wt[cc][o0 + 4];
            u64 wp[8] = {pack2(w0.x), pack2(w0.y), pack2(w0.z), pack2(w0.w),
                         pack2(w1.x), pack2(w1.y), pack2(w1.z), pack2(w1.w)};
            ulonglong2 ia = *(const ulonglong2*)&it[cc][n0];
            ulonglong2 ib = *(const ulonglong2*)&it[cc][n0 + 4];
            u64 iv[4] = {ia.x, ia.y, ib.x, ib.y};
            #pragma unroll
            for (int j = 0; j < 8; j++)
                #pragma unroll
                for (int i = 0; i < 4; i++)
                    ffma2(acc[j][i], wp[j], iv[i]);
        }
    }

    float val[8][8];
    #pragma unroll
    for (int j = 0; j < 8; j++) {
        float bb = bias[o0 + j];
        float2 p0 = unpack2(acc[j][0]);
        float2 p1 = unpack2(acc[j][1]);
        float2 p2 = unpack2(acc[j][2]);
        float2 p3 = unpack2(acc[j][3]);
        val[j][0] = p0.x + bb; val[j][1] = p0.y + bb;
        val[j][2] = p1.x + bb; val[j][3] = p1.y + bb;
        val[j][4] = p2.x + bb; val[j][5] = p2.y + bb;
        val[j][6] = p3.x + bb; val[j][7] = p3.y + bb;
    }

    #pragma unroll
    for (int i = 0; i < 8; i++) {
        uint32_t hi[4], mi[4];
        #pragma unroll
        for (int jp = 0; jp < 4; jp++) {
            float v0 = val[2*jp][i], v1 = val[2*jp+1][i];
            __nv_bfloat16 h0 = __float2bfloat16(v0);
            __nv_bfloat16 m0 = __float2bfloat16(v0 - __bfloat162float(h0));
            __nv_bfloat16 h1 = __float2bfloat16(v1);
            __nv_bfloat16 m1 = __float2bfloat16(v1 - __bfloat162float(h1));
            hi[jp] = (uint32_t)__bfloat16_as_ushort(h0) | ((uint32_t)__bfloat16_as_ushort(h1) << 16);
            mi[jp] = (uint32_t)__bfloat16_as_ushort(m0) | ((uint32_t)__bfloat16_as_ushort(m1) << 16);
        }
        __nv_bfloat16* rowp = (which ? g_ks : g_qs)
                            + ((size_t)(b * NN + nb + n0 + i)) * 128 + o0;
        *(uint4*)(rowp)      = make_uint4(hi[0], hi[1], hi[2], hi[3]);
        *(uint4*)(rowp + 64) = make_uint4(mi[0], mi[1], mi[2], mi[3]);
    }
}

// ===========================================================================
// Attention (round-12 loop, 3-deep K pipeline, ONE sync per tile):
// stores RAW exp(e), accumulates row sums, writes g_inv.
// CTA = 128 q-rows x 2048 cols, 256 thr = 8 warps:
//   warp = (rw 0..3: 32 rows = 2 m16 tiles, cg 0..1: 8 nt subtiles).
// 3-buffer safety: per-iter barrier bounds thread skew to <1 iteration, so
// the prefetch target buf (mt+1)%3 is never concurrently read (readers touch
// only bufs (mt-1)%3 and mt%3).
// ===========================================================================
#define QROW  272
#define SQ    0
#define SK0   34816
#define SKB   34816                  // per K buffer
#define SSUM  (SK0 + 3*SKB)          // 139264: 2*128 floats
#define SM_TOTAL (SSUM + 1024)

__global__ __launch_bounds__(256, 1) void attention_kernel(float* __restrict__ att)
{
    extern __shared__ char smem[];
    const uint32_t sb = smem_u32(smem);
    const int t    = threadIdx.x;
    const int wid  = t >> 5;
    const int lane = t & 31;
    const int rw   = wid & 3;
    const int cg   = wid >> 2;
    const int nb   = blockIdx.x * 128;
    const int b    = blockIdx.y;
    const int r0   = rw * 32;

    {
        const char* ksrc = (const char*)(g_ks + ((size_t)(b * NN)) * 128);
        #pragma unroll
        for (int i = 0; i < 8; i++) {
            int id  = t + i * 256;
            int row = id >> 4, c16 = id & 15;
            CP_ASYNC16(sb + SK0 + row * QROW + c16 * 16, ksrc + row * 256 + c16 * 16);
        }
        CP_COMMIT();
        const char* qsrc = (const char*)(g_qs + ((size_t)(b * NN + nb)) * 128);
        #pragma unroll
        for (int i = 0; i < 8; i++) {
            int id  = t + i * 256;
            int row = id >> 4, c16 = id & 15;
            *(uint4*)(smem + SQ + row * QROW + c16 * 16) =
                *(const uint4*)(qsrc + row * 256 + c16 * 16);
        }
    }
    __syncthreads();

    // A fragments: a[comp][ks][rowtile][4]
    uint32_t a[2][4][2][4];
    #pragma unroll
    for (int rt = 0; rt < 2; rt++) {
        uint32_t qaddr = sb + SQ + (uint32_t)(r0 + rt * 16 + (lane & 15)) * QROW
                       + ((lane >> 4) & 1) * 16;
        #pragma unroll
        for (int c = 0; c < 2; c++)
            #pragma unroll
            for (int ks = 0; ks < 4; ks++)
                LDSM_X4(a[c][ks][rt][0], a[c][ks][rt][1], a[c][ks][rt][2], a[c][ks][rt][3],
                        qaddr + c * 128 + ks * 32);
    }

    const uint32_t kb4_lane = (uint32_t)((lane & 7) * QROW
                             + ((lane >> 3) & 1) * 16 + (lane >> 4) * 32);
    const int g = lane >> 2;
    const int cpair = (lane & 3) * 2;
    float s[2][2];
    s[0][0] = s[0][1] = s[1][0] = s[1][1] = 0.0f;
    float* rowp[2][2];
    #pragma unroll
    for (int rt = 0; rt < 2; rt++) {
        rowp[rt][0] = att + ((size_t)(b * NN + nb + r0 + rt * 16 + g)) * NN;
        rowp[rt][1] = rowp[rt][0] + 8 * NN;
    }

    int buf = 0;
    for (int mt = 0; mt < 16; mt++) {
        if (mt + 1 < 16) {
            const char* ksrc = (const char*)(g_ks + ((size_t)(b * NN + (mt + 1) * 128)) * 128);
            int nbuf = (buf + 1 == 3) ? 0 : buf + 1;
            uint32_t dst = sb + SK0 + (uint32_t)nbuf * SKB;
            #pragma unroll
            for (int i = 0; i < 8; i++) {
                int id  = t + i * 256;
                int row = id >> 4, c16 = id & 15;
                CP_ASYNC16(dst + row * QROW + c16 * 16, ksrc + row * 256 + c16 * 16);
            }
            CP_COMMIT();
            asm volatile("cp.async.wait_group 1;" ::: "memory");
        } else {
            asm volatile("cp.async.wait_group 0;" ::: "memory");
        }
        __syncthreads();   // tile mt data visible; single barrier per tile

        const uint32_t kbase = sb + SK0 + (uint32_t)buf * SKB + kb4_lane;
        const int mcol = mt * 128;

        #pragma unroll 4
        for (int nt8 = 0; nt8 < 8; nt8++) {
            const int nt = cg * 8 + nt8;
            uint32_t bb[2][4][2];
            uint32_t baddr = kbase + (uint32_t)nt * (8 * QROW);
            #pragma unroll
            for (int c = 0; c < 2; c++)
                #pragma unroll
                for (int ksp = 0; ksp < 2; ksp++)
                    LDSM_X4(bb[c][2*ksp][0], bb[c][2*ksp][1],
                            bb[c][2*ksp+1][0], bb[c][2*ksp+1][1],
                            baddr + c * 128 + ksp * 64);

            float hh[2][4] = {{0,0,0,0},{0,0,0,0}};
            float hm[2][4] = {{0,0,0,0},{0,0,0,0}};
            float mh[2][4] = {{0,0,0,0},{0,0,0,0}};
            #pragma unroll
            for (int ks = 0; ks < 4; ks++)
                #pragma unroll
                for (int rt = 0; rt < 2; rt++) {
                    mma_bf16(hh[rt][0], hh[rt][1], hh[rt][2], hh[rt][3],
                             a[0][ks][rt][0], a[0][ks][rt][1], a[0][ks][rt][2], a[0][ks][rt][3],
                             bb[0][ks][0], bb[0][ks][1]);
                    mma_bf16(hm[rt][0], hm[rt][1], hm[rt][2], hm[rt][3],
                             a[0][ks][rt][0], a[0][ks][rt][1], a[0][ks][rt][2], a[0][ks][rt][3],
                             bb[1][ks][0], bb[1][ks][1]);
                    mma_bf16(mh[rt][0], mh[rt][1], mh[rt][2], mh[rt][3],
                             a[1][ks][rt][0], a[1][ks][rt][1], a[1][ks][rt][2], a[1][ks][rt][3],
                             bb[0][ks][0], bb[0][ks][1]);
                }
            const int col = mcol + nt * 8 + cpair;
            #pragma unroll
            for (int rt = 0; rt < 2; rt++) {
                float c0 = (hh[rt][0] + hm[rt][0]) + mh[rt][0];
                float c1 = (hh[rt][1] + hm[rt][1]) + mh[rt][1];
                float c2 = (hh[rt][2] + hm[rt][2]) + mh[rt][2];
                float c3 = (hh[rt][3] + hm[rt][3]) + mh[rt][3];
                float e0 = __expf(c0), e1 = __expf(c1);
                float e2 = __expf(c2), e3 = __expf(c3);
                s[rt][0] += e0 + e1;
                s[rt][1] += e2 + e3;
                *(float2*)(rowp[rt][0] + col) = make_float2(e0, e1);
                *(float2*)(rowp[rt][1] + col) = make_float2(e2, e3);
            }
        }
        buf = (buf + 1 == 3) ? 0 : buf + 1;
    }

    // quad-reduce partial sums, stash per-cg, merge -> g_inv
    float* sums = (float*)(smem + SSUM);
    #pragma unroll
    for (int rt = 0; rt < 2; rt++) {
        float lo = s[rt][0], hi = s[rt][1];
        lo += __shfl_xor_sync(0xffffffffu, lo, 1);
        lo += __shfl_xor_sync(0xffffffffu, lo, 2);
        hi += __shfl_xor_sync(0xffffffffu, hi, 1);
        hi += __shfl_xor_sync(0xffffffffu, hi, 2);
        if ((lane & 3) == 0) {
            sums[cg * 128 + r0 + rt * 16 + g]     = lo;
            sums[cg * 128 + r0 + rt * 16 + g + 8] = hi;
        }
    }
    __syncthreads();
    if (t < 128)
        g_inv[b * NN + nb + t] = 1.0f / (sums[t] + sums[128 + t]);
}

// ---------------------------------------------------------------------------
// Rescale: att[b][row][*] *= g_inv[b][row].  Full-occupancy coalesced RMW.
// ---------------------------------------------------------------------------
__global__ __launch_bounds__(256) void rescale_kernel(float* __restrict__ att)
{
    const int row = blockIdx.x;
    const int b   = blockIdx.y;
    const float inv = g_inv[b * NN + row];
    float4* p = (float4*)(att + ((size_t)(b * NN + row)) * NN);
    const int t = threadIdx.x;
    #pragma unroll
    for (int i = 0; i < 2; i++) {
        float4 v = p[t + i * 256];
        v.x *= inv; v.y *= inv; v.z *= inv; v.w *= inv;
        p[t + i * 256] = v;
    }
}

// ---------------------------------------------------------------------------
// AV GEMM (slow path): out = gamma*(V@att^T) + x; 64 CTAs, internal loops
// ---------------------------------------------------------------------------
__global__ __launch_bounds__(128) void av_kernel(const float* __restrict__ att,
                                                 const float* __restrict__ x,
                                                 const float* __restrict__ gate,
                                                 float* __restrict__ out)
{
    const float gm = gate[0];
    if (gm == 0.0f) return;
    const int t  = threadIdx.x;
    const int tx = t & 7;
    const int ty = t >> 3;
    const int n0 = tx * 8;
    const int c0 = ty * 4;
    const int b  = blockIdx.y;

    __shared__ float vT[32][68];
    __shared__ float aT[32][68];

    for (int nbi = 0; nbi < 4; nbi++) {
        const int nb = (blockIdx.x * 4 + nbi) * 64;
        for (int cbi = 0; cbi < 8; cbi++) {
            const int cb = cbi * 64;
            float acc[4][8];
            #pragma unroll
            for (int o = 0; o < 4; o++)
                #pragma unroll
                for (int n = 0; n < 8; n++) acc[o][n] = 0.0f;

            for (int mc = 0; mc < NN; mc += 32) {
                __syncthreads();
                #pragma unroll
                for (int i = 0; i < 4; i++) {
                    int l  = t + i * 128;
                    int c  = l >> 3;
                    int m4 = (l & 7) * 4;
                    float4 v = *(const float4*)&g_v[((size_t)b * CCH + cb + c) * NN + mc + m4];
                    vT[m4 + 0][c] = v.x; vT[m4 + 1][c] = v.y;
                    vT[m4 + 2][c] = v.z; vT[m4 + 3][c] = v.w;
                    float4 aa = *(const float4*)&att[((size_t)(b * NN + nb + c)) * NN + mc + m4];
                    aT[m4 + 0][c] = aa.x; aT[m4 + 1][c] = aa.y;
                    aT[m4 + 2][c] = aa.z; aT[m4 + 3][c] = aa.w;
                }
                __syncthreads();
                #pragma unroll 8
                for (int mm = 0; mm < 32; mm++) {
                    float4 vv = *(const float4*)&vT[mm][c0];
                    float4 a0 = *(const float4*)&aT[mm][n0];
                    float4 a1 = *(const float4*)&aT[mm][n0 + 4];
                    float v[4] = {vv.x, vv.y, vv.z, vv.w};
                    float aa[8] = {a0.x, a0.y, a0.z, a0.w, a1.x, a1.y, a1.z, a1.w};
                    #pragma unroll
                    for (int o = 0; o < 4; o++)
                        #pragma unroll
                        for (int n = 0; n < 8; n++)
                            acc[o][n] = fmaf(v[o], aa[n], acc[o][n]);
                }
            }

            #pragma unroll
            for (int o = 0; o < 4; o++) {
                size_t gidx = ((size_t)b * CCH + cb + c0 + o) * NN + nb + n0;
                float4 x0 = *(const float4*)&x[gidx];
                float4 x1 = *(const float4*)&x[gidx + 4];
                *(float4*)&out[gidx] = make_float4(
                    fmaf(gm, acc[o][0], x0.x), fmaf(gm, acc[o][1], x0.y),
                    fmaf(gm, acc[o][2], x0.z), fmaf(gm, acc[o][3], x0.w));
                *(float4*)&out[gidx + 4] = make_float4(
                    fmaf(gm, acc[o][4], x1.x), fmaf(gm, acc[o][5], x1.y),
                    fmaf(gm, acc[o][6], x1.z), fmaf(gm, acc[o][7], x1.w));
            }
        }
    }
}

// ---------------------------------------------------------------------------
extern "C" void kernel_launch(void* const* d_in, const int* in_sizes, int n_in,
                              void* d_out, int out_size)
{
    (void)in_sizes; (void)n_in; (void)out_size;
    const float* x     = (const float*)d_in[0];
    const float* y     = (const float*)d_in[1];
    const float* Wq    = (const float*)d_in[2];
    const float* bq    = (const float*)d_in[3];
    const float* Wk    = (const float*)d_in[4];
    const float* bk    = (const float*)d_in[5];
    const float* Wv    = (const float*)d_in[6];
    const float* bv    = (const float*)d_in[7];
    const float* gamma = (const float*)d_in[8];

    float* out = (float*)d_out;
    float* att = out + OUT_OFF;

    cudaFuncSetAttribute(attention_kernel,
                         cudaFuncAttributeMaxDynamicSharedMemorySize, SM_TOTAL);

    // idx 0: q(z=0), k(z=1, + out=x copy), v(z=2, gated) — one launch
    qkv_kernel<<<dim3(NN/128, BB, 3), 128>>>(x, y, Wq, bq, Wk, bk, Wv, bv, gamma, out);
    // idx 1: attention — raw exp(e) + row sums -> g_inv
    attention_kernel<<<dim3(16, BB), 256, SM_TOTAL>>>(att);
    // idx 2: rescale att by 1/S (DRAM-roofline pass)
    rescale_kernel<<<dim3(NN, BB), 256>>>(att);
    // idx 3: out = gamma*(V@att^T) + x (gated)
    av_kernel<<<dim3(8, BB), 128>>>(att, x, gamma, out);
}

// round 16
// speedup vs baseline: 1.5619x; 1.0378x over previous
#include <cuda_runtime.h>
#include <cuda_bf16.h>
#include <math.h>
#include <cstdint>

// Problem constants
#define BB   8
#define CCH  512
#define C8   64
#define NN   2048
#define OUT_OFF (BB*CCH*NN)   // start of attention region in d_out (floats)
#define LOG2E 1.4426950408889634f

typedef unsigned long long u64;

// Scratch: q/k as 2-way bf16 split [b][n][comp*64 + o], comp 0=hi, 1=mid
// q splits are pre-scaled by log2(e) so attention uses ex2 directly.
__device__ __nv_bfloat16 g_qs[BB*NN*128];
__device__ __nv_bfloat16 g_ks[BB*NN*128];
__device__ float g_inv[BB*NN];             // per-row 1/sum(exp2(e'))
__device__ float g_v[BB*CCH*NN];           // slow path only (gamma != 0)

// ---- packed f32x2 helpers ------------------------------------------------
__device__ __forceinline__ u64 pack2(float x) {
    u64 r; asm("mov.b64 %0, {%1, %1};" : "=l"(r) : "f"(x)); return r;
}
__device__ __forceinline__ void ffma2(u64& d, u64 a, u64 b) {
    asm("fma.rn.f32x2 %0, %1, %2, %3;" : "=l"(d) : "l"(a), "l"(b), "l"(d));
}
__device__ __forceinline__ float2 unpack2(u64 v) {
    float2 f; asm("mov.b64 {%0, %1}, %2;" : "=f"(f.x), "=f"(f.y) : "l"(v)); return f;
}
__device__ __forceinline__ float ex2f(float x) {
    float r; asm("ex2.approx.f32 %0, %1;" : "=f"(r) : "f"(x)); return r;
}

// ---- sm_80-class tensor helpers (legal on plain sm_103 target) -----------
__device__ __forceinline__ uint32_t smem_u32(const void* p) {
    uint32_t a;
    asm("{ .reg .u64 t; cvta.to.shared.u64 t, %1; cvt.u32.u64 %0, t; }" : "=r"(a) : "l"(p));
    return a;
}
#define LDSM_X4(r0, r1, r2, r3, addr) \
    asm volatile("ldmatrix.sync.aligned.m8n8.x4.shared.b16 {%0,%1,%2,%3}, [%4];" \
        : "=r"(r0), "=r"(r1), "=r"(r2), "=r"(r3) : "r"(addr))
#define CP_ASYNC16(dst, src) \
    asm volatile("cp.async.cg.shared.global [%0], [%1], 16;" :: "r"(dst), "l"(src) : "memory")
#define CP_COMMIT() asm volatile("cp.async.commit_group;" ::: "memory")

__device__ __forceinline__ void mma_bf16(float& c0, float& c1, float& c2, float& c3,
                                         uint32_t a0, uint32_t a1, uint32_t a2, uint32_t a3,
                                         uint32_t b0, uint32_t b1) {
    asm volatile(
        "mma.sync.aligned.m16n8k16.row.col.f32.bf16.bf16.f32 "
        "{%0,%1,%2,%3}, {%4,%5,%6,%7}, {%8,%9}, {%0,%1,%2,%3};"
        : "+f"(c0), "+f"(c1), "+f"(c2), "+f"(c3)
        : "r"(a0), "r"(a1), "r"(a2), "r"(a3), "r"(b0), "r"(b1));
}

// ---------------------------------------------------------------------------
// Fused q/k/v projections in one launch.
//   z=0: q = log2e*(Wq*y+bq)   z=1: k = Wk*x+bk (+ out = x copy)   z=2: v (gated)
// q/k: FFMA2 -> 2-way bf16 split, layout [b][n][comp*64+o].
// ---------------------------------------------------------------------------
__global__ __launch_bounds__(128, 3) void qkv_kernel(
    const float* __restrict__ x, const float* __restrict__ y,
    const float* __restrict__ Wq, const float* __restrict__ bq,
    const float* __restrict__ Wk, const float* __restrict__ bk,
    const float* __restrict__ Wv, const float* __restrict__ bv,
    const float* __restrict__ gamma, float* __restrict__ outx)
{
    __shared__ float wt[32][68];
    __shared__ float it[32][128];
    __shared__ float inT[32][68];
    __shared__ float wT [32][68];

    const int which = blockIdx.z;
    const int t  = threadIdx.x;
    const int b  = blockIdx.y;

    if (which == 2) {
        // ---- v projection (gated on gamma != 0) ----
        if (gamma[0] == 0.0f) return;
        const int tx = t & 7;
        const int ty = t >> 3;
        const int n0 = tx * 8;
        const int o0 = ty * 4;

        for (int nbi = 0; nbi < 2; nbi++) {
            const int nb = blockIdx.x * 128 + nbi * 64;
            for (int obi = 0; obi < 8; obi++) {
                const int ob = obi * 64;
                float acc[4][8];
                #pragma unroll
                for (int o = 0; o < 4; o++)
                    #pragma unroll
                    for (int n = 0; n < 8; n++) acc[o][n] = 0.0f;

                for (int c0 = 0; c0 < CCH; c0 += 32) {
                    __syncthreads();
                    #pragma unroll
                    for (int i = 0; i < 4; i++) {
                        int l  = t + i * 128;
                        int cc = l >> 4;
                        int n4 = (l & 15) * 4;
                        *(float4*)&inT[cc][n4] =
                            *(const float4*)&y[((b * CCH + c0 + cc) * NN) + nb + n4];
                    }
                    #pragma unroll
                    for (int i = 0; i < 4; i++) {
                        int l  = t + i * 128;
                        int o  = l >> 3;
                        int c4 = (l & 7) * 4;
                        float4 w4 = *(const float4*)&Wv[(ob + o) * CCH + c0 + c4];
                        wT[c4 + 0][o] = w4.x; wT[c4 + 1][o] = w4.y;
                        wT[c4 + 2][o] = w4.z; wT[c4 + 3][o] = w4.w;
                    }
                    __syncthreads();
                    #pragma unroll 8
                    for (int cc = 0; cc < 32; cc++) {
                        float4 wv = *(const float4*)&wT[cc][o0];
                        float4 a0 = *(const float4*)&inT[cc][n0];
                        float4 a1 = *(const float4*)&inT[cc][n0 + 4];
                        float w[4] = {wv.x, wv.y, wv.z, wv.w};
                        float v[8] = {a0.x, a0.y, a0.z, a0.w, a1.x, a1.y, a1.z, a1.w};
                        #pragma unroll
                        for (int o = 0; o < 4; o++)
                            #pragma unroll
                            for (int n = 0; n < 8; n++)
                                acc[o][n] = fmaf(w[o], v[n], acc[o][n]);
                    }
                }

                #pragma unroll
                for (int o = 0; o < 4; o++) {
                    int row = ob + o0 + o;
                    float bb = bv[row];
                    float* op = &g_v[((size_t)b * CCH + row) * NN + nb + n0];
                    *(float4*)op       = make_float4(acc[o][0]+bb, acc[o][1]+bb, acc[o][2]+bb, acc[o][3]+bb);
                    *(float4*)(op + 4) = make_float4(acc[o][4]+bb, acc[o][5]+bb, acc[o][6]+bb, acc[o][7]+bb);
                }
            }
        }
        return;
    }

    // ---- q/k projection (FFMA2, bf16 split) ----
    const float* in   = which ? x  : y;
    const float* W    = which ? Wk : Wq;
    const float* bias = which ? bk : bq;
    const float scale = which ? 1.0f : LOG2E;   // q pre-scaled by log2(e)

    const int tx = t & 15;
    const int ty = t >> 4;
    const int n0 = tx * 8;
    const int o0 = ty * 8;
    const int nb = blockIdx.x * 128;

    u64 acc[8][4];
    #pragma unroll
    for (int j = 0; j < 8; j++)
        #pragma unroll
        for (int i = 0; i < 4; i++) acc[j][i] = 0ull;

    for (int c0 = 0; c0 < CCH; c0 += 32) {
        __syncthreads();
        #pragma unroll
        for (int i = 0; i < 4; i++) {
            int l  = t + i * 128;
            int o  = l >> 3;
            int c4 = (l & 7) * 4;
            float4 w4 = *(const float4*)&W[o * CCH + c0 + c4];
            wt[c4 + 0][o] = w4.x; wt[c4 + 1][o] = w4.y;
            wt[c4 + 2][o] = w4.z; wt[c4 + 3][o] = w4.w;
        }
        #pragma unroll
        for (int i = 0; i < 8; i++) {
            int l  = t + i * 128;
            int cc = l >> 5;
            int n4 = (l & 31) * 4;
            size_t gidx = ((size_t)(b * CCH + c0 + cc) * NN) + nb + n4;
            float4 v = *(const float4*)&in[gidx];
            *(float4*)&it[cc][n4] = v;
            if (which) *(float4*)&outx[gidx] = v;   // out = x (residual copy)
        }
        __syncthreads();

        #pragma unroll 4
        for (int cc = 0; cc < 32; cc++) {
            float4 w0 = *(const float4*)&wt[cc][o0];
            float4 w1 = *(const float4*)&wt[cc][o0 + 4];
            u64 wp[8] = {pack2(w0.x), pack2(w0.y), pack2(w0.z), pack2(w0.w),
                         pack2(w1.x), pack2(w1.y), pack2(w1.z), pack2(w1.w)};
            ulonglong2 ia = *(const ulonglong2*)&it[cc][n0];
            ulonglong2 ib = *(const ulonglong2*)&it[cc][n0 + 4];
            u64 iv[4] = {ia.x, ia.y, ib.x, ib.y};
            #pragma unroll
            for (int j = 0; j < 8; j++)
                #pragma unroll
                for (int i = 0; i < 4; i++)
                    ffma2(acc[j][i], wp[j], iv[i]);
        }
    }

    float val[8][8];
    #pragma unroll
    for (int j = 0; j < 8; j++) {
        float bb = bias[o0 + j];
        float2 p0 = unpack2(acc[j][0]);
        float2 p1 = unpack2(acc[j][1]);
        float2 p2 = unpack2(acc[j][2]);
        float2 p3 = unpack2(acc[j][3]);
        val[j][0] = (p0.x + bb) * scale; val[j][1] = (p0.y + bb) * scale;
        val[j][2] = (p1.x + bb) * scale; val[j][3] = (p1.y + bb) * scale;
        val[j][4] = (p2.x + bb) * scale; val[j][5] = (p2.y + bb) * scale;
        val[j][6] = (p3.x + bb) * scale; val[j][7] = (p3.y + bb) * scale;
    }

    #pragma unroll
    for (int i = 0; i < 8; i++) {
        uint32_t hi[4], mi[4];
        #pragma unroll
        for (int jp = 0; jp < 4; jp++) {
            float v0 = val[2*jp][i], v1 = val[2*jp+1][i];
            __nv_bfloat16 h0 = __float2bfloat16(v0);
            __nv_bfloat16 m0 = __float2bfloat16(v0 - __bfloat162float(h0));
            __nv_bfloat16 h1 = __float2bfloat16(v1);
            __nv_bfloat16 m1 = __float2bfloat16(v1 - __bfloat162float(h1));
            hi[jp] = (uint32_t)__bfloat16_as_ushort(h0) | ((uint32_t)__bfloat16_as_ushort(h1) << 16);
            mi[jp] = (uint32_t)__bfloat16_as_ushort(m0) | ((uint32_t)__bfloat16_as_ushort(m1) << 16);
        }
        __nv_bfloat16* rowp = (which ? g_ks : g_qs)
                            + ((size_t)(b * NN + nb + n0 + i)) * 128 + o0;
        *(uint4*)(rowp)      = make_uint4(hi[0], hi[1], hi[2], hi[3]);
        *(uint4*)(rowp + 64) = make_uint4(mi[0], mi[1], mi[2], mi[3]);
    }
}

// ===========================================================================
// Attention (3-deep K pipeline, one sync/tile): stores RAW exp2(e'),
// accumulates row sums, writes g_inv.  Rescale kernel normalizes.
// CTA = 128 q-rows x 2048 cols, 256 thr = 8 warps:
//   warp = (rw 0..3: 32 rows = 2 m16 tiles, cg 0..1: 8 nt subtiles).
// ===========================================================================
#define QROW  272
#define SQ    0
#define SK0   34816
#define SKB   34816                  // per K buffer
#define SSUM  (SK0 + 3*SKB)          // 2*128 floats
#define SM_TOTAL (SSUM + 1024)

__global__ __launch_bounds__(256, 1) void attention_kernel(float* __restrict__ att)
{
    extern __shared__ char smem[];
    const uint32_t sb = smem_u32(smem);
    const int t    = threadIdx.x;
    const int wid  = t >> 5;
    const int lane = t & 31;
    const int rw   = wid & 3;
    const int cg   = wid >> 2;
    const int nb   = blockIdx.x * 128;
    const int b    = blockIdx.y;
    const int r0   = rw * 32;

    {
        const char* ksrc = (const char*)(g_ks + ((size_t)(b * NN)) * 128);
        #pragma unroll
        for (int i = 0; i < 8; i++) {
            int id  = t + i * 256;
            int row = id >> 4, c16 = id & 15;
            CP_ASYNC16(sb + SK0 + row * QROW + c16 * 16, ksrc + row * 256 + c16 * 16);
        }
        CP_COMMIT();
        const char* qsrc = (const char*)(g_qs + ((size_t)(b * NN + nb)) * 128);
        #pragma unroll
        for (int i = 0; i < 8; i++) {
            int id  = t + i * 256;
            int row = id >> 4, c16 = id & 15;
            *(uint4*)(smem + SQ + row * QROW + c16 * 16) =
                *(const uint4*)(qsrc + row * 256 + c16 * 16);
        }
    }
    __syncthreads();

    // A fragments: a[comp][ks][rowtile][4]
    uint32_t a[2][4][2][4];
    #pragma unroll
    for (int rt = 0; rt < 2; rt++) {
        uint32_t qaddr = sb + SQ + (uint32_t)(r0 + rt * 16 + (lane & 15)) * QROW
                       + ((lane >> 4) & 1) * 16;
        #pragma unroll
        for (int c = 0; c < 2; c++)
            #pragma unroll
            for (int ks = 0; ks < 4; ks++)
                LDSM_X4(a[c][ks][rt][0], a[c][ks][rt][1], a[c][ks][rt][2], a[c][ks][rt][3],
                        qaddr + c * 128 + ks * 32);
    }

    const uint32_t kb4_lane = (uint32_t)((lane & 7) * QROW
                             + ((lane >> 3) & 1) * 16 + (lane >> 4) * 32);
    const int g = lane >> 2;
    const int cpair = (lane & 3) * 2;
    float s[2][2];
    s[0][0] = s[0][1] = s[1][0] = s[1][1] = 0.0f;
    float* rowp[2][2];
    #pragma unroll
    for (int rt = 0; rt < 2; rt++) {
        rowp[rt][0] = att + ((size_t)(b * NN + nb + r0 + rt * 16 + g)) * NN;
        rowp[rt][1] = rowp[rt][0] + 8 * NN;
    }

    int buf = 0;
    for (int mt = 0; mt < 16; mt++) {
        if (mt + 1 < 16) {
            const char* ksrc = (const char*)(g_ks + ((size_t)(b * NN + (mt + 1) * 128)) * 128);
            int nbuf = (buf + 1 == 3) ? 0 : buf + 1;
            uint32_t dst = sb + SK0 + (uint32_t)nbuf * SKB;
            #pragma unroll
            for (int i = 0; i < 8; i++) {
                int id  = t + i * 256;
                int row = id >> 4, c16 = id & 15;
                CP_ASYNC16(dst + row * QROW + c16 * 16, ksrc + row * 256 + c16 * 16);
            }
            CP_COMMIT();
            asm volatile("cp.async.wait_group 1;" ::: "memory");
        } else {
            asm volatile("cp.async.wait_group 0;" ::: "memory");
        }
        __syncthreads();

        const uint32_t kbase = sb + SK0 + (uint32_t)buf * SKB + kb4_lane;
        const int mcol = mt * 128;

        #pragma unroll 4
        for (int nt8 = 0; nt8 < 8; nt8++) {
            const int nt = cg * 8 + nt8;
            uint32_t bb[2][4][2];
            uint32_t baddr = kbase + (uint32_t)nt * (8 * QROW);
            #pragma unroll
            for (int c = 0; c < 2; c++)
                #pragma unroll
                for (int ksp = 0; ksp < 2; ksp++)
                    LDSM_X4(bb[c][2*ksp][0], bb[c][2*ksp][1],
                            bb[c][2*ksp+1][0], bb[c][2*ksp+1][1],
                            baddr + c * 128 + ksp * 64);

            float hh[2][4] = {{0,0,0,0},{0,0,0,0}};
            float hm[2][4] = {{0,0,0,0},{0,0,0,0}};
            float mh[2][4] = {{0,0,0,0},{0,0,0,0}};
            #pragma unroll
            for (int ks = 0; ks < 4; ks++)
                #pragma unroll
                for (int rt = 0; rt < 2; rt++) {
                    mma_bf16(hh[rt][0], hh[rt][1], hh[rt][2], hh[rt][3],
                             a[0][ks][rt][0], a[0][ks][rt][1], a[0][ks][rt][2], a[0][ks][rt][3],
                             bb[0][ks][0], bb[0][ks][1]);
                    mma_bf16(hm[rt][0], hm[rt][1], hm[rt][2], hm[rt][3],
                             a[0][ks][rt][0], a[0][ks][rt][1], a[0][ks][rt][2], a[0][ks][rt][3],
                             bb[1][ks][0], bb[1][ks][1]);
                    mma_bf16(mh[rt][0], mh[rt][1], mh[rt][2], mh[rt][3],
                             a[1][ks][rt][0], a[1][ks][rt][1], a[1][ks][rt][2], a[1][ks][rt][3],
                             bb[0][ks][0], bb[0][ks][1]);
                }
            const int col = mcol + nt * 8 + cpair;
            #pragma unroll
            for (int rt = 0; rt < 2; rt++) {
                float c0 = (hh[rt][0] + hm[rt][0]) + mh[rt][0];
                float c1 = (hh[rt][1] + hm[rt][1]) + mh[rt][1];
                float c2 = (hh[rt][2] + hm[rt][2]) + mh[rt][2];
                float c3 = (hh[rt][3] + hm[rt][3]) + mh[rt][3];
                float e0 = ex2f(c0), e1 = ex2f(c1);
                float e2 = ex2f(c2), e3 = ex2f(c3);
                s[rt][0] += e0 + e1;
                s[rt][1] += e2 + e3;
                *(float2*)(rowp[rt][0] + col) = make_float2(e0, e1);
                *(float2*)(rowp[rt][1] + col) = make_float2(e2, e3);
            }
        }
        buf = (buf + 1 == 3) ? 0 : buf + 1;
    }

    // quad-reduce partial sums, stash per-cg, merge -> g_inv
    float* sums = (float*)(smem + SSUM);
    #pragma unroll
    for (int rt = 0; rt < 2; rt++) {
        float lo = s[rt][0], hi = s[rt][1];
        lo += __shfl_xor_sync(0xffffffffu, lo, 1);
        lo += __shfl_xor_sync(0xffffffffu, lo, 2);
        hi += __shfl_xor_sync(0xffffffffu, hi, 1);
        hi += __shfl_xor_sync(0xffffffffu, hi, 2);
        if ((lane & 3) == 0) {
            sums[cg * 128 + r0 + rt * 16 + g]     = lo;
            sums[cg * 128 + r0 + rt * 16 + g + 8] = hi;
        }
    }
    __syncthreads();
    if (t < 128)
        g_inv[b * NN + nb + t] = 1.0f / (sums[t] + sums[128 + t]);
}

// ---------------------------------------------------------------------------
// Rescale: att[b][row][*] *= g_inv[b][row].  2 rows/block, 4 independent
// float4 RMWs per thread (MLP 4) for DRAM-roofline throughput.
// ---------------------------------------------------------------------------
__global__ __launch_bounds__(256) void rescale_kernel(float* __restrict__ att)
{
    const int r0 = blockIdx.x * 2;
    const int b  = blockIdx.y;
    const int t  = threadIdx.x;
    const float inv0 = g_inv[b * NN + r0];
    const float inv1 = g_inv[b * NN + r0 + 1];
    float4* p0 = (float4*)(att + ((size_t)(b * NN + r0)) * NN);
    float4* p1 = p0 + (NN / 4);
    float4 v00 = p0[t], v01 = p0[t + 256];
    float4 v10 = p1[t], v11 = p1[t + 256];
    v00.x *= inv0; v00.y *= inv0; v00.z *= inv0; v00.w *= inv0;
    v01.x *= inv0; v01.y *= inv0; v01.z *= inv0; v01.w *= inv0;
    v10.x *= inv1; v10.y *= inv1; v10.z *= inv1; v10.w *= inv1;
    v11.x *= inv1; v11.y *= inv1; v11.z *= inv1; v11.w *= inv1;
    p0[t] = v00; p0[t + 256] = v01;
    p1[t] = v10; p1[t + 256] = v11;
}

// ---------------------------------------------------------------------------
// AV GEMM (slow path): out = gamma*(V@att^T) + x; 64 CTAs, internal loops
// ---------------------------------------------------------------------------
__global__ __launch_bounds__(128) void av_kernel(const float* __restrict__ att,
                                                 const float* __restrict__ x,
                                                 const float* __restrict__ gate,
                                                 float* __restrict__ out)
{
    const float gm = gate[0];
    if (gm == 0.0f) return;
    const int t  = threadIdx.x;
    const int tx = t & 7;
    const int ty = t >> 3;
    const int n0 = tx * 8;
    const int c0 = ty * 4;
    const int b  = blockIdx.y;

    __shared__ float vT[32][68];
    __shared__ float aT[32][68];

    for (int nbi = 0; nbi < 4; nbi++) {
        const int nb = (blockIdx.x * 4 + nbi) * 64;
        for (int cbi = 0; cbi < 8; cbi++) {
            const int cb = cbi * 64;
            float acc[4][8];
            #pragma unroll
            for (int o = 0; o < 4; o++)
                #pragma unroll
                for (int n = 0; n < 8; n++) acc[o][n] = 0.0f;

            for (int mc = 0; mc < NN; mc += 32) {
                __syncthreads();
                #pragma unroll
                for (int i = 0; i < 4; i++) {
                    int l  = t + i * 128;
                    int c  = l >> 3;
                    int m4 = (l & 7) * 4;
                    float4 v = *(const float4*)&g_v[((size_t)b * CCH + cb + c) * NN + mc + m4];
                    vT[m4 + 0][c] = v.x; vT[m4 + 1][c] = v.y;
                    vT[m4 + 2][c] = v.z; vT[m4 + 3][c] = v.w;
                    float4 aa = *(const float4*)&att[((size_t)(b * NN + nb + c)) * NN + mc + m4];
                    aT[m4 + 0][c] = aa.x; aT[m4 + 1][c] = aa.y;
                    aT[m4 + 2][c] = aa.z; aT[m4 + 3][c] = aa.w;
                }
                __syncthreads();
                #pragma unroll 8
                for (int mm = 0; mm < 32; mm++) {
                    float4 vv = *(const float4*)&vT[mm][c0];
                    float4 a0 = *(const float4*)&aT[mm][n0];
                    float4 a1 = *(const float4*)&aT[mm][n0 + 4];
                    float v[4] = {vv.x, vv.y, vv.z, vv.w};
                    float aa[8] = {a0.x, a0.y, a0.z, a0.w, a1.x, a1.y, a1.z, a1.w};
                    #pragma unroll
                    for (int o = 0; o < 4; o++)
                        #pragma unroll
                        for (int n = 0; n < 8; n++)
                            acc[o][n] = fmaf(v[o], aa[n], acc[o][n]);
                }
            }

            #pragma unroll
            for (int o = 0; o < 4; o++) {
                size_t gidx = ((size_t)b * CCH + cb + c0 + o) * NN + nb + n0;
                float4 x0 = *(const float4*)&x[gidx];
                float4 x1 = *(const float4*)&x[gidx + 4];
                *(float4*)&out[gidx] = make_float4(
                    fmaf(gm, acc[o][0], x0.x), fmaf(gm, acc[o][1], x0.y),
                    fmaf(gm, acc[o][2], x0.z), fmaf(gm, acc[o][3], x0.w));
                *(float4*)&out[gidx + 4] = make_float4(
                    fmaf(gm, acc[o][4], x1.x), fmaf(gm, acc[o][5], x1.y),
                    fmaf(gm, acc[o][6], x1.z), fmaf(gm, acc[o][7], x1.w));
            }
        }
    }
}

// ---------------------------------------------------------------------------
extern "C" void kernel_launch(void* const* d_in, const int* in_sizes, int n_in,
                              void* d_out, int out_size)
{
    (void)in_sizes; (void)n_in; (void)out_size;
    const float* x     = (const float*)d_in[0];
    const float* y     = (const float*)d_in[1];
    const float* Wq    = (const float*)d_in[2];
    const float* bq    = (const float*)d_in[3];
    const float* Wk    = (const float*)d_in[4];
    const float* bk    = (const float*)d_in[5];
    const float* Wv    = (const float*)d_in[6];
    const float* bv    = (const float*)d_in[7];
    const float* gamma = (const float*)d_in[8];

    float* out = (float*)d_out;
    float* att = out + OUT_OFF;

    cudaFuncSetAttribute(attention_kernel,
                         cudaFuncAttributeMaxDynamicSharedMemorySize, SM_TOTAL);

    // idx 0: q(z=0, pre-scaled by log2e), k(z=1, + out=x copy), v(z=2, gated)
    qkv_kernel<<<dim3(NN/128, BB, 3), 128>>>(x, y, Wq, bq, Wk, bk, Wv, bv, gamma, out);
    // idx 1: attention — raw exp2(e') + row sums -> g_inv
    attention_kernel<<<dim3(16, BB), 256, SM_TOTAL>>>(att);
    // idx 2: rescale att by 1/S (DRAM-roofline pass, MLP 4)
    rescale_kernel<<<dim3(NN/2, BB), 256>>>(att);
    // idx 3: out = gamma*(V@att^T) + x (gated)
    av_kernel<<<dim3(8, BB), 128>>>(att, x, gamma, out);
}